// round 16
// baseline (speedup 1.0000x reference)
#include <cuda_runtime.h>
#include <cstdint>

// VTBPR fused kernel (R16): 256-bit loads/stores (sm_103a .v8.b32).
//   score[b] = item_beta[i] + user_beta[u] + <ug,ig> + <tv,vf_b> + <tt,tf_b>
//   metapath[b,0,p,l,:] = ug if path_type==0, ig if ==1, else 0
//
// d_out = [ score (B floats) | metapath (B*16*512 floats) ]
//
// R2-R15 established: DRAM mixed-stream floor ~5.5TB/s, invariant to
// occupancy (26-88%), STG vs UBLKCP, L2 policies, ordering, batching.
// Last untried lever: request WIDTH. sm_103a supports v8.b32 global
// ld/st (LDG.256/STG.256). 64 threads/row own 8 contiguous floats each:
// one LDG.256 per input vector, one STG.256 per output segment -- half
// the store instructions, double the payload per request. 4 rows per
// 256-thread CTA with per-row named barriers (2-warp scope).

#define HIDDEN 512
#define PL     16
#define TPR    64             // threads per row (8 floats each)
#define RPC    4              // rows per CTA
#define NT     (TPR * RPC)    // 256

__device__ __forceinline__ void ld8(const float* a,
                                    float& v0, float& v1, float& v2, float& v3,
                                    float& v4, float& v5, float& v6, float& v7) {
    asm("ld.global.v8.b32 {%0,%1,%2,%3,%4,%5,%6,%7}, [%8];"
        : "=f"(v0), "=f"(v1), "=f"(v2), "=f"(v3),
          "=f"(v4), "=f"(v5), "=f"(v6), "=f"(v7)
        : "l"(a));
}

__device__ __forceinline__ void st8(float* a,
                                    float v0, float v1, float v2, float v3,
                                    float v4, float v5, float v6, float v7) {
    asm volatile("st.global.v8.b32 [%0], {%1,%2,%3,%4,%5,%6,%7,%8};"
                 :: "l"(a), "f"(v0), "f"(v1), "f"(v2), "f"(v3),
                    "f"(v4), "f"(v5), "f"(v6), "f"(v7) : "memory");
}

__global__ void __launch_bounds__(NT, 4)
vtbpr_kernel(const float* __restrict__ user_gama,
             const float* __restrict__ item_gama,
             const float* __restrict__ user_beta,
             const float* __restrict__ item_beta,
             const float* __restrict__ theta_user_visual,
             const float* __restrict__ theta_user_text,
             const float* __restrict__ visual_features,
             const float* __restrict__ textural_features,
             const int*   __restrict__ user_idx,
             const int*   __restrict__ item_idx,
             const int*   __restrict__ path_type,
             float* __restrict__ out,
             int B)
{
    const int tid  = threadIdx.x;          // 0..255
    const int sub  = tid >> 6;             // row 0..3 within CTA
    const int lane = tid & (TPR - 1);      // 0..63 within row
    const int b    = blockIdx.x * RPC + sub;

    __shared__ int   pt[RPC][PL];
    __shared__ float wsum[RPC][2];

    const int u = user_idx[b];
    const int i = item_idx[b];

    if (lane < PL) pt[sub][lane] = path_type[b * PL + lane];
    const float ub = user_beta[u];
    const float ib = item_beta[i];

    const int off = lane * 8;   // this thread's 8-float slice

    // ---- ug/ig: one LDG.256 each; kept live through the scatter ----
    float ug0,ug1,ug2,ug3,ug4,ug5,ug6,ug7;
    float ig0,ig1,ig2,ig3,ig4,ig5,ig6,ig7;
    ld8(user_gama + (size_t)u * HIDDEN + off, ug0,ug1,ug2,ug3,ug4,ug5,ug6,ug7);
    ld8(item_gama + (size_t)i * HIDDEN + off, ig0,ig1,ig2,ig3,ig4,ig5,ig6,ig7);

    float partial = ug0*ig0 + ug1*ig1 + ug2*ig2 + ug3*ig3
                  + ug4*ig4 + ug5*ig5 + ug6*ig6 + ug7*ig7;

    // ---- tv/vf phase (registers reused) ----
    {
        float a0,a1,a2,a3,a4,a5,a6,a7, c0,c1,c2,c3,c4,c5,c6,c7;
        ld8(theta_user_visual + (size_t)u * HIDDEN + off, a0,a1,a2,a3,a4,a5,a6,a7);
        ld8(visual_features   + (size_t)b * HIDDEN + off, c0,c1,c2,c3,c4,c5,c6,c7);
        partial += a0*c0 + a1*c1 + a2*c2 + a3*c3 + a4*c4 + a5*c5 + a6*c6 + a7*c7;
    }

    // ---- tt/tf phase ----
    {
        float a0,a1,a2,a3,a4,a5,a6,a7, c0,c1,c2,c3,c4,c5,c6,c7;
        ld8(theta_user_text   + (size_t)u * HIDDEN + off, a0,a1,a2,a3,a4,a5,a6,a7);
        ld8(textural_features + (size_t)b * HIDDEN + off, c0,c1,c2,c3,c4,c5,c6,c7);
        partial += a0*c0 + a1*c1 + a2*c2 + a3*c3 + a4*c4 + a5*c5 + a6*c6 + a7*c7;
    }

    // ---- reduce across this row's 2 warps ----
    #pragma unroll
    for (int o = 16; o > 0; o >>= 1)
        partial += __shfl_xor_sync(0xFFFFFFFFu, partial, o);

    if ((lane & 31) == 0) wsum[sub][lane >> 5] = partial;

    // Per-row barrier (2 warps): orders pt STS + wsum.
    asm volatile("bar.sync %0, %1;" :: "r"(1 + sub), "r"(TPR) : "memory");

    if (lane == 0)
        out[b] = ub + ib + wsum[sub][0] + wsum[sub][1];

    // ---- Metapath scatter: one STG.256 per segment per thread ----
    float* mp = out + B + (size_t)b * PL * HIDDEN + off;

    #pragma unroll
    for (int j = 0; j < PL; j++) {
        const int t = pt[sub][j];
        float* dst = mp + (size_t)j * HIDDEN;
        if (t == 0)      st8(dst, ug0,ug1,ug2,ug3,ug4,ug5,ug6,ug7);
        else if (t == 1) st8(dst, ig0,ig1,ig2,ig3,ig4,ig5,ig6,ig7);
        else             st8(dst, 0.f,0.f,0.f,0.f,0.f,0.f,0.f,0.f);
    }
}

extern "C" void kernel_launch(void* const* d_in, const int* in_sizes, int n_in,
                              void* d_out, int out_size)
{
    const float* user_gama          = (const float*)d_in[0];
    const float* item_gama          = (const float*)d_in[1];
    const float* user_beta          = (const float*)d_in[2];
    const float* item_beta          = (const float*)d_in[3];
    const float* theta_user_visual  = (const float*)d_in[4];
    const float* theta_user_text    = (const float*)d_in[5];
    const float* visual_features    = (const float*)d_in[6];
    const float* textural_features  = (const float*)d_in[7];
    const int*   user_idx           = (const int*)d_in[8];
    const int*   item_idx           = (const int*)d_in[9];
    const int*   path_type          = (const int*)d_in[10];

    const int B = in_sizes[8];  // 8192 (divisible by RPC)

    vtbpr_kernel<<<B / RPC, NT>>>(user_gama, item_gama, user_beta, item_beta,
                                  theta_user_visual, theta_user_text,
                                  visual_features, textural_features,
                                  user_idx, item_idx, path_type,
                                  (float*)d_out, B);
}

// round 17
// speedup vs baseline: 1.0449x; 1.0449x over previous
#include <cuda_runtime.h>
#include <cstdint>

// VTBPR fused kernel (FINAL, frozen R13): 2 rows per 256-thread CTA,
// per-row named barriers, evict_last reads, STG.128 scatter.
//   score[b] = item_beta[i] + user_beta[u] + <ug,ig> + <tv,vf_b> + <tt,tf_b>
//   metapath[b,0,p,l,:] = ug if path_type==0, ig if ==1, else 0
//
// d_out = [ score (B floats) | metapath (B*16*512 floats) ]
//
// Sweep (R2-R16, 15 variants): kernel is pinned at the DRAM mixed-stream
// floor (~5.5TB/s; 268MB irreducible writes + ~42MB reads). Falsified:
// occupancy (26-88%), STG.256, UBLKCP bulk store, all L2 read/write
// policies, store ordering, 1/4/8-row batching, 32/64-thread rows.
// Optimum: 128 threads/row, 2 rows/CTA, narrow named barriers. This
// exact kernel measured 59.87us wall twice (best).

#define HIDDEN 512
#define VEC    (HIDDEN / 4)   // 128 float4 lanes per row
#define PL     16             // P*L
#define NT     256            // threads per CTA (2 rows)

__device__ __forceinline__ uint64_t policy_evict_last() {
    uint64_t p;
    asm("createpolicy.fractional.L2::evict_last.b64 %0, 1.0;" : "=l"(p));
    return p;
}

__device__ __forceinline__ float4 ld_el(const float4* a, uint64_t pol) {
    float4 v;
    asm("ld.global.L2::cache_hint.v4.f32 {%0,%1,%2,%3}, [%4], %5;"
        : "=f"(v.x), "=f"(v.y), "=f"(v.z), "=f"(v.w)
        : "l"(a), "l"(pol));
    return v;
}

__global__ void __launch_bounds__(NT, 4)
vtbpr_kernel(const float* __restrict__ user_gama,
             const float* __restrict__ item_gama,
             const float* __restrict__ user_beta,
             const float* __restrict__ item_beta,
             const float* __restrict__ theta_user_visual,
             const float* __restrict__ theta_user_text,
             const float* __restrict__ visual_features,
             const float* __restrict__ textural_features,
             const int*   __restrict__ user_idx,
             const int*   __restrict__ item_idx,
             const int*   __restrict__ path_type,
             float* __restrict__ out,
             int B)
{
    const int tid  = threadIdx.x;          // 0..255
    const int half = tid >> 7;             // 0/1: which row this half owns
    const int lane = tid & (VEC - 1);      // 0..127 within the row
    const int b    = blockIdx.x * 2 + half;

    __shared__ int   pt[2][PL];
    __shared__ float wsum[2][VEC / 32];

    const int u = user_idx[b];
    const int i = item_idx[b];

    // Each half stages its OWN row's path types (lanes 0..15 of the half).
    if (lane < PL) pt[half][lane] = path_type[b * PL + lane];
    const float ub = user_beta[u];
    const float ib = item_beta[i];

    const uint64_t pol = policy_evict_last();

    const float4* ug_p = (const float4*)(user_gama         + (size_t)u * HIDDEN);
    const float4* ig_p = (const float4*)(item_gama         + (size_t)i * HIDDEN);
    const float4* tv_p = (const float4*)(theta_user_visual + (size_t)u * HIDDEN);
    const float4* tt_p = (const float4*)(theta_user_text   + (size_t)u * HIDDEN);
    const float4* vf_p = (const float4*)(visual_features   + (size_t)b * HIDDEN);
    const float4* tf_p = (const float4*)(textural_features + (size_t)b * HIDDEN);

    // Front-batch all six vector loads (max MLP), pinned evict_last in L2.
    const float4 ug4 = ld_el(&ug_p[lane], pol);
    const float4 ig4 = ld_el(&ig_p[lane], pol);
    const float4 tv4 = ld_el(&tv_p[lane], pol);
    const float4 tt4 = ld_el(&tt_p[lane], pol);
    const float4 vf4 = ld_el(&vf_p[lane], pol);
    const float4 tf4 = ld_el(&tf_p[lane], pol);

    // Dot products + warp reduce
    float partial =
        ug4.x * ig4.x + ug4.y * ig4.y + ug4.z * ig4.z + ug4.w * ig4.w +
        tv4.x * vf4.x + tv4.y * vf4.y + tv4.z * vf4.z + tv4.w * vf4.w +
        tt4.x * tf4.x + tt4.y * tf4.y + tt4.z * tf4.z + tt4.w * tf4.w;

    #pragma unroll
    for (int off = 16; off > 0; off >>= 1)
        partial += __shfl_xor_sync(0xFFFFFFFFu, partial, off);

    if ((tid & 31) == 0) wsum[half][(tid >> 5) & 3] = partial;

    // Per-row barrier: only this row's 4 warps synchronize (pt + wsum).
    asm volatile("bar.sync %0, %1;" :: "r"(1 + half), "r"(VEC) : "memory");

    if (lane == 0) {
        float s = ub + ib;
        #pragma unroll
        for (int w = 0; w < VEC / 32; w++) s += wsum[half][w];
        out[b] = s;
    }

    // Metapath scatter: 16 coalesced STG.128 per thread for this row.
    float4* mp = (float4*)(out + B + (size_t)b * PL * HIDDEN);
    const float4 zero4 = make_float4(0.f, 0.f, 0.f, 0.f);

    #pragma unroll
    for (int j = 0; j < PL; j++) {
        const int t = pt[half][j];
        const float4 v = (t == 0) ? ug4 : ((t == 1) ? ig4 : zero4);
        mp[(size_t)j * VEC + lane] = v;
    }
}

extern "C" void kernel_launch(void* const* d_in, const int* in_sizes, int n_in,
                              void* d_out, int out_size)
{
    const float* user_gama          = (const float*)d_in[0];
    const float* item_gama          = (const float*)d_in[1];
    const float* user_beta          = (const float*)d_in[2];
    const float* item_beta          = (const float*)d_in[3];
    const float* theta_user_visual  = (const float*)d_in[4];
    const float* theta_user_text    = (const float*)d_in[5];
    const float* visual_features    = (const float*)d_in[6];
    const float* textural_features  = (const float*)d_in[7];
    const int*   user_idx           = (const int*)d_in[8];
    const int*   item_idx           = (const int*)d_in[9];
    const int*   path_type          = (const int*)d_in[10];

    const int B = in_sizes[8];  // 8192 (even)

    vtbpr_kernel<<<B / 2, NT>>>(user_gama, item_gama, user_beta, item_beta,
                                theta_user_visual, theta_user_text,
                                visual_features, textural_features,
                                user_idx, item_idx, path_type,
                                (float*)d_out, B);
}